// round 13
// baseline (speedup 1.0000x reference)
#include <cuda_runtime.h>
#include <cuda_bf16.h>
#include <cstdint>

#define N_NODES 100000
#define D 128
#define E_MAX 1600000
#define SCAN_CHUNK 1024
#define SCAN_NB ((N_NODES + SCAN_CHUNK - 1) / SCAN_CHUNK)   // 98
#define N_TILES ((N_NODES + 127) / 128)                      // 782 (row padding for planes)
#define PLANE_ROWS ((size_t)N_TILES * 128)                   // 100096 rows
#define PLANE_ELEMS (PLANE_ROWS * 128)
#define MTILE 256
#define N_TILES256 ((N_NODES + MTILE - 1) / MTILE)           // 391

// ---------------- scratch (static device globals; no allocation) ----------------
__device__ float g_h0[(size_t)N_NODES * D];
__device__ float g_h1[(size_t)N_NODES * D];
// split-bf16 operand planes: X (feat, later h1), Y (h0), Z (agg)
__device__ __nv_bfloat16 g_pXhi[PLANE_ELEMS], g_pXlo[PLANE_ELEMS];
__device__ __nv_bfloat16 g_pYhi[PLANE_ELEMS], g_pYlo[PLANE_ELEMS];
__device__ __nv_bfloat16 g_pZhi[PLANE_ELEMS], g_pZlo[PLANE_ELEMS];
__device__ int   g_hist[2][N_NODES];
__device__ int   g_rowptr[2][N_NODES + 1];
__device__ int   g_cursor[2][N_NODES];
__device__ int   g_csr[2][E_MAX];
__device__ int   g_blocksums[2][SCAN_NB];
// pre-split weights, transposed (B[n][k] = W[k][n]), plain row-major [n][128] bf16
__device__ __nv_bfloat16 g_w[5][2][128 * 128];

// ---------------- host-side streams/events (host resources only; created once) ------
static cudaStream_t g_s2 = nullptr;
static cudaEvent_t  g_evFork = nullptr, g_evCsr0 = nullptr, g_evCsr1 = nullptr;
static void ensure_host_resources() {
    if (g_s2) return;
    cudaStreamCreateWithFlags(&g_s2, cudaStreamNonBlocking);
    cudaEventCreateWithFlags(&g_evFork, cudaEventDisableTiming);
    cudaEventCreateWithFlags(&g_evCsr0, cudaEventDisableTiming);
    cudaEventCreateWithFlags(&g_evCsr1, cudaEventDisableTiming);
}
static struct _InitOnce { _InitOnce() { ensure_host_resources(); } } g_initOnce;

// ================= helpers =================
__device__ __forceinline__ uint32_t smem_u32(const void* p) {
    uint32_t a;
    asm("{ .reg .u64 t; cvta.to.shared.u64 t, %1; cvt.u32.u64 %0, t; }" : "=r"(a) : "l"(p));
    return a;
}
__device__ __forceinline__ uint32_t pack_bf16x2(float x, float y) {
    uint32_t r;
    asm("cvt.rn.bf16x2.f32 %0, %1, %2;" : "=r"(r) : "f"(y), "f"(x));
    return r;
}
__device__ __forceinline__ void cp_async16(uint32_t dst, const void* src) {
    asm volatile("cp.async.cg.shared.global [%0], [%1], 16;" :: "r"(dst), "l"(src));
}
// [128B-row x 64-col bf16] tile chunks, XOR-swizzled by (r & 7) — verified since R6
__device__ __forceinline__ uint32_t chunk_off64(int r, int c) {
    return (uint32_t)r * 128u + (uint32_t)((c ^ (r & 7)) << 4);
}
__device__ __forceinline__ void ldsm_x4(uint32_t* f, uint32_t addr) {
    asm volatile("ldmatrix.sync.aligned.m8n8.x4.shared.b16 {%0,%1,%2,%3}, [%4];"
                 : "=r"(f[0]), "=r"(f[1]), "=r"(f[2]), "=r"(f[3]) : "r"(addr));
}
__device__ __forceinline__ void ldsm_x2(uint32_t* f, uint32_t addr) {
    asm volatile("ldmatrix.sync.aligned.m8n8.x2.shared.b16 {%0,%1}, [%2];"
                 : "=r"(f[0]), "=r"(f[1]) : "r"(addr));
}
__device__ __forceinline__ void mma_bf16(float* c, const uint32_t* a, const uint32_t* b) {
    asm volatile("mma.sync.aligned.m16n8k16.row.col.f32.bf16.bf16.f32 "
                 "{%0,%1,%2,%3}, {%4,%5,%6,%7}, {%8,%9}, {%0,%1,%2,%3};"
                 : "+f"(c[0]), "+f"(c[1]), "+f"(c[2]), "+f"(c[3])
                 : "r"(a[0]), "r"(a[1]), "r"(a[2]), "r"(a[3]), "r"(b[0]), "r"(b[1]));
}

// ================= weight prep (all 5 matrices in one launch) =================
__global__ void prep_w_all_kernel(const float* __restrict__ w0, const float* __restrict__ w1,
                                  const float* __restrict__ w2, const float* __restrict__ w3,
                                  const float* __restrict__ w4, __nv_bfloat16* __restrict__ out) {
    int g = blockIdx.x >> 6;                      // 64 blocks per matrix
    const float* W = (g == 0) ? w0 : (g == 1) ? w1 : (g == 2) ? w2 : (g == 3) ? w3 : w4;
    __nv_bfloat16* hi = out + (size_t)g * 2 * 16384;
    __nv_bfloat16* lo = hi + 16384;
    int e = (blockIdx.x & 63) * 256 + threadIdx.x;   // 0..16383
    int n = e >> 7, k = e & 127;
    float v = W[k * 128 + n];
    float h = __bfloat162float(__float2bfloat16_rn(v));
    hi[n * 128 + k] = __float2bfloat16_rn(h);
    lo[n * 128 + k] = __float2bfloat16_rn(v - h);
}

// ================= feat prep: fp32 [M][128] -> hi/lo planes (zero tail rows) =========
__global__ void prep_feat_kernel(const float* __restrict__ A,
                                 __nv_bfloat16* __restrict__ hi, __nv_bfloat16* __restrict__ lo,
                                 int M) {
    int id = blockIdx.x * 256 + threadIdx.x;     // one per 16B out-chunk: PLANE_ROWS*16
    if (id >= (int)(PLANE_ROWS * 16)) return;
    int r = id >> 4, c = id & 15;                // row, chunk (cols 8c..8c+7)
    float4 v0 = make_float4(0.f, 0.f, 0.f, 0.f), v1 = v0;
    if (r < M) {
        const float4* gp = (const float4*)(A + (size_t)r * 128 + c * 8);
        v0 = gp[0]; v1 = gp[1];
    }
    float h0 = __bfloat162float(__float2bfloat16_rn(v0.x));
    float h1 = __bfloat162float(__float2bfloat16_rn(v0.y));
    float h2 = __bfloat162float(__float2bfloat16_rn(v0.z));
    float h3 = __bfloat162float(__float2bfloat16_rn(v0.w));
    float h4 = __bfloat162float(__float2bfloat16_rn(v1.x));
    float h5 = __bfloat162float(__float2bfloat16_rn(v1.y));
    float h6 = __bfloat162float(__float2bfloat16_rn(v1.z));
    float h7 = __bfloat162float(__float2bfloat16_rn(v1.w));
    uint4 hp, lp;
    hp.x = pack_bf16x2(h0, h1); hp.y = pack_bf16x2(h2, h3);
    hp.z = pack_bf16x2(h4, h5); hp.w = pack_bf16x2(h6, h7);
    lp.x = pack_bf16x2(v0.x - h0, v0.y - h1);
    lp.y = pack_bf16x2(v0.z - h2, v0.w - h3);
    lp.z = pack_bf16x2(v1.x - h4, v1.y - h5);
    lp.w = pack_bf16x2(v1.z - h6, v1.w - h7);
    *(uint4*)((char*)hi + (size_t)r * 256 + c * 16) = hp;
    *(uint4*)((char*)lo + (size_t)r * 256 + c * 16) = lp;
}

// ================= split-bf16 GEMM: M=256 tile, double-buffered cp.async pipeline =====
// 512 threads = 16 warps (4 m-slots x 4 n-slots), warp tile 64x32 (R11-verified mapping).
// smem: 2 buffers x 96KB; per buffer: A_HI 32KB, A_LO 32KB, B_HI 16KB, B_LO 16KB.
#define AQ_HI 0
#define AQ_LO 32768
#define BQ_HI 65536
#define BQ_LO 81920
#define BUFSZ 98304
#define SMEM_MMA (2 * BUFSZ)
#define GTHREADS 512

// stage one K=64 half (pure cp.async: A 4096 chunks, B 2048 chunks)
__device__ __forceinline__ void stage_planes(
    const __nv_bfloat16* __restrict__ Ahi, const __nv_bfloat16* __restrict__ Alo,
    const __nv_bfloat16* __restrict__ Bhi, const __nv_bfloat16* __restrict__ Blo,
    uint32_t buf, int block_m, int kh, int tid)
{
#pragma unroll
    for (int j = 0; j < 4; j++) {                // B: 2048 chunks (hi 1024 + lo 1024)
        int id = tid + j * GTHREADS;
        const char* plane = (const char*)((id & 1024) ? Blo : Bhi);
        int cid = id & 1023;
        int n = cid >> 3, c = cid & 7;
        cp_async16(buf + ((id & 1024) ? BQ_LO : BQ_HI) + chunk_off64(n, c),
                   plane + (size_t)n * 256 + kh * 128 + c * 16);
    }
#pragma unroll
    for (int j = 0; j < 8; j++) {                // A: 4096 chunks (hi 2048 + lo 2048)
        int id = tid + j * GTHREADS;
        const char* plane = (const char*)((id & 2048) ? Alo : Ahi);
        int cid = id & 2047;
        int r = cid >> 3, c = cid & 7;
        cp_async16(buf + ((id & 2048) ? AQ_LO : AQ_HI) + chunk_off64(r, c),
                   plane + (size_t)(block_m + r) * 256 + kh * 128 + c * 16);
    }
    asm volatile("cp.async.commit_group;");
}

// one K=64 half of accumulation (R11-verified M=256 mapping)
__device__ __forceinline__ void mma_half(uint32_t buf, int wid, int lane, float acc[4][4][4]) {
    const int m_base = (wid & 3) * 64;
    const int n_base = (wid >> 2) * 32;
    const int ra = lane & 15;
    const int kca = lane >> 4;
    const int nb = lane & 7;
    const int kcb = (lane >> 3) & 1;
#pragma unroll
    for (int kk = 0; kk < 4; kk++) {
        uint32_t bh[4][2], bl[4][2];
#pragma unroll
        for (int in = 0; in < 4; in++) {
            int n = n_base + in * 8 + nb;
            uint32_t a = buf + chunk_off64(n, 2 * kk + kcb);
            ldsm_x2(bh[in], a + BQ_HI);
            ldsm_x2(bl[in], a + BQ_LO);
        }
#pragma unroll
        for (int im = 0; im < 4; im++) {
            uint32_t ah[4], al[4];
            int r = m_base + im * 16 + ra;
            uint32_t a = buf + chunk_off64(r, 2 * kk + kca);
            ldsm_x4(ah, a + AQ_HI);
            ldsm_x4(al, a + AQ_LO);
#pragma unroll
            for (int in = 0; in < 4; in++) {
                mma_bf16(acc[im][in], ah, bh[in]);
                mma_bf16(acc[im][in], ah, bl[in]);
                mma_bf16(acc[im][in], al, bh[in]);
            }
        }
    }
}

// DUAL: C = act(A1@W1 [+ A2@W2] + bias); PLANES: also emit split planes of C
template<int DUAL, int RELU, int PLANES>
__global__ void __launch_bounds__(GTHREADS, 1) gemm_mma_kernel(
    const __nv_bfloat16* __restrict__ A1hi, const __nv_bfloat16* __restrict__ A1lo,
    const __nv_bfloat16* __restrict__ B1hi, const __nv_bfloat16* __restrict__ B1lo,
    const __nv_bfloat16* __restrict__ A2hi, const __nv_bfloat16* __restrict__ A2lo,
    const __nv_bfloat16* __restrict__ B2hi, const __nv_bfloat16* __restrict__ B2lo,
    const float* __restrict__ bias, float* __restrict__ C,
    __nv_bfloat16* __restrict__ Chi, __nv_bfloat16* __restrict__ Clo, int M)
{
    extern __shared__ __align__(128) char smem[];
    const uint32_t sb = smem_u32(smem);
    const int tid = threadIdx.x;
    const int wid = tid >> 5;
    const int lane = tid & 31;
    const int block_m = blockIdx.x * MTILE;

    float acc[4][4][4];
#pragma unroll
    for (int im = 0; im < 4; im++)
#pragma unroll
        for (int in = 0; in < 4; in++)
#pragma unroll
            for (int q = 0; q < 4; q++) acc[im][in][q] = 0.0f;

    const __nv_bfloat16* AH[2] = {A1hi, A2hi};
    const __nv_bfloat16* AL[2] = {A1lo, A2lo};
    const __nv_bfloat16* BH[2] = {B1hi, B2hi};
    const __nv_bfloat16* BL[2] = {B1lo, B2lo};
    constexpr int NH = DUAL ? 4 : 2;

    // prologue: stage half 0 into buffer 0
    stage_planes(AH[0], AL[0], BH[0], BL[0], sb, block_m, 0, tid);

#pragma unroll
    for (int i = 0; i < NH; i++) {
        if (i + 1 < NH) {
            int m = (i + 1) >> 1, kh = (i + 1) & 1;
            stage_planes(AH[m], AL[m], BH[m], BL[m],
                         sb + ((i + 1) & 1) * BUFSZ, block_m, kh, tid);
            asm volatile("cp.async.wait_group 1;" ::: "memory");
        } else {
            asm volatile("cp.async.wait_group 0;" ::: "memory");
        }
        __syncthreads();
        mma_half(sb + (i & 1) * BUFSZ, wid, lane, acc);
        __syncthreads();
    }

    // epilogue
    const int m_base = block_m + (wid & 3) * 64;
    const int n_base = (wid >> 2) * 32;
    const int rq = lane >> 2;
    const int cq = (lane & 3) * 2;
#pragma unroll
    for (int im = 0; im < 4; im++) {
#pragma unroll
        for (int in = 0; in < 4; in++) {
            int gn = n_base + in * 8 + cq;
            float bx = bias[gn], by = bias[gn + 1];
#pragma unroll
            for (int half = 0; half < 2; half++) {
                int gm = m_base + im * 16 + rq + half * 8;
                if (gm >= M) continue;
                float x = acc[im][in][half * 2 + 0] + bx;
                float y = acc[im][in][half * 2 + 1] + by;
                if (RELU) { x = fmaxf(x, 0.f); y = fmaxf(y, 0.f); }
                size_t idx = (size_t)gm * 128 + gn;
                *(float2*)(C + idx) = make_float2(x, y);
                if (PLANES) {
                    float hx = __bfloat162float(__float2bfloat16_rn(x));
                    float hy = __bfloat162float(__float2bfloat16_rn(y));
                    *(uint32_t*)(Chi + idx) = pack_bf16x2(hx, hy);
                    *(uint32_t*)(Clo + idx) = pack_bf16x2(x - hx, y - hy);
                }
            }
        }
    }
}

// ================= graph aggregation =================
__global__ void zero_int_kernel(int* __restrict__ p, int n) {
    int i = blockIdx.x * blockDim.x + threadIdx.x;
    int stride = gridDim.x * blockDim.x;
    for (; i < n; i += stride) p[i] = 0;
}

__global__ void hist_kernel(const int* __restrict__ dst, int* __restrict__ hist, int E) {
    int i = blockIdx.x * blockDim.x + threadIdx.x;
    if (i >= E) return;
    atomicAdd(&hist[dst[i]], 1);
}

__global__ void scan1_kernel(const int* __restrict__ hist, int* __restrict__ blocksums) {
    __shared__ int sh[256];
    int t = threadIdx.x;
    int base = blockIdx.x * SCAN_CHUNK + t * 4;
    int s = 0;
#pragma unroll
    for (int j = 0; j < 4; j++) {
        int idx = base + j;
        if (idx < N_NODES) s += hist[idx];
    }
    sh[t] = s;
    __syncthreads();
    for (int o = 128; o > 0; o >>= 1) {
        if (t < o) sh[t] += sh[t + o];
        __syncthreads();
    }
    if (t == 0) blocksums[blockIdx.x] = sh[0];
}

__global__ void scan2_kernel(int* __restrict__ blocksums, int nb, int* __restrict__ rowptr) {
    if (threadIdx.x == 0 && blockIdx.x == 0) {
        int run = 0;
        for (int i = 0; i < nb; i++) {
            int v = blocksums[i];
            blocksums[i] = run;
            run += v;
        }
        rowptr[N_NODES] = run;
    }
}

__global__ void scan3_kernel(const int* __restrict__ hist, const int* __restrict__ blocksums,
                             int* __restrict__ rowptr, int* __restrict__ cursor) {
    __shared__ int sh[256];
    int t = threadIdx.x;
    int base = blockIdx.x * SCAN_CHUNK + t * 4;
    int v[4];
    int s = 0;
#pragma unroll
    for (int j = 0; j < 4; j++) {
        int idx = base + j;
        v[j] = (idx < N_NODES) ? hist[idx] : 0;
        s += v[j];
    }
    sh[t] = s;
    __syncthreads();
    int val = s;
    for (int o = 1; o < 256; o <<= 1) {
        int other = (t >= o) ? sh[t - o] : 0;
        __syncthreads();
        val += other;
        sh[t] = val;
        __syncthreads();
    }
    int texcl = val - s;
    int off = blocksums[blockIdx.x] + texcl;
#pragma unroll
    for (int j = 0; j < 4; j++) {
        int idx = base + j;
        if (idx < N_NODES) {
            rowptr[idx] = off;
            cursor[idx] = off;
        }
        off += v[j];
    }
}

__global__ void fill_kernel(const int* __restrict__ src, const int* __restrict__ dst,
                            int* __restrict__ cursor, int* __restrict__ csr, int E) {
    int i = blockIdx.x * blockDim.x + threadIdx.x;
    if (i >= E) return;
    int p = atomicAdd(&cursor[dst[i]], 1);
    csr[p] = src[i];
}

// gather + mean; writes split-bf16 planes (R12-verified)
__global__ void __launch_bounds__(256) gather_mean_kernel(
    const float* __restrict__ h, const int* __restrict__ csr,
    const int* __restrict__ rowptr,
    __nv_bfloat16* __restrict__ Ahi, __nv_bfloat16* __restrict__ Alo)
{
    int gw = (blockIdx.x * blockDim.x + threadIdx.x) >> 5;
    int lane = threadIdx.x & 31;
    if (gw >= N_NODES) return;
    int n0 = rowptr[gw];
    int n1 = rowptr[gw + 1];
    float4 acc = make_float4(0.f, 0.f, 0.f, 0.f);
    for (int base = n0; base < n1; base += 32) {
        int idx = base + lane;
        int sj = (idx < n1) ? csr[idx] : 0;
        int cnt = min(32, n1 - base);
        for (int t = 0; t < cnt; t++) {
            int s = __shfl_sync(0xFFFFFFFFu, sj, t);
            float4 v = ((const float4*)(h + (size_t)s * 128))[lane];
            acc.x += v.x; acc.y += v.y; acc.z += v.z; acc.w += v.w;
        }
    }
    float inv = (n1 > n0) ? 1.0f / (float)(n1 - n0) : 0.0f;
    acc.x *= inv; acc.y *= inv; acc.z *= inv; acc.w *= inv;
    float hx = __bfloat162float(__float2bfloat16_rn(acc.x));
    float hy = __bfloat162float(__float2bfloat16_rn(acc.y));
    float hz = __bfloat162float(__float2bfloat16_rn(acc.z));
    float hw = __bfloat162float(__float2bfloat16_rn(acc.w));
    size_t idx = (size_t)gw * 128 + lane * 4;
    uint2 hp, lp;
    hp.x = pack_bf16x2(hx, hy);            hp.y = pack_bf16x2(hz, hw);
    lp.x = pack_bf16x2(acc.x - hx, acc.y - hy);
    lp.y = pack_bf16x2(acc.z - hz, acc.w - hw);
    *(uint2*)(Ahi + idx) = hp;
    *(uint2*)(Alo + idx) = lp;
}

__global__ void score_kernel(const float* __restrict__ h,
                             const int* __restrict__ pa, const int* __restrict__ pb, int P,
                             const int* __restrict__ na, const int* __restrict__ nb, int Q,
                             float* __restrict__ out)
{
    int gw = (blockIdx.x * blockDim.x + threadIdx.x) >> 5;
    int lane = threadIdx.x & 31;
    if (gw >= P + Q) return;
    int ia, ib;
    if (gw < P) { ia = pa[gw]; ib = pb[gw]; }
    else        { ia = na[gw - P]; ib = nb[gw - P]; }
    float4 va = ((const float4*)(h + (size_t)ia * 128))[lane];
    float4 vb = ((const float4*)(h + (size_t)ib * 128))[lane];
    float s = va.x * vb.x + va.y * vb.y + va.z * vb.z + va.w * vb.w;
#pragma unroll
    for (int o = 16; o > 0; o >>= 1) s += __shfl_xor_sync(0xFFFFFFFFu, s, o);
    if (lane == 0) out[gw] = s;
}

// ---------------- CSR build (all launches on stream s) ----------------
static void build_csr(cudaStream_t s, const int* src, const int* dst, int E,
                      int* hist, int* rowptr, int* cursor, int* csr, int* blocksums)
{
    hist_kernel<<<(E + 255) / 256, 256, 0, s>>>(dst, hist, E);
    scan1_kernel<<<SCAN_NB, 256, 0, s>>>(hist, blocksums);
    scan2_kernel<<<1, 32, 0, s>>>(blocksums, SCAN_NB, rowptr);
    scan3_kernel<<<SCAN_NB, 256, 0, s>>>(hist, blocksums, rowptr, cursor);
    fill_kernel<<<(E + 255) / 256, 256, 0, s>>>(src, dst, cursor, csr, E);
}

extern "C" void kernel_launch(void* const* d_in, const int* in_sizes, int n_in,
                              void* d_out, int out_size)
{
    const float* feat    = (const float*)d_in[0];
    const int*   e0s     = (const int*)d_in[1];
    const int*   e0d     = (const int*)d_in[2];
    const int*   e1s     = (const int*)d_in[3];
    const int*   e1d     = (const int*)d_in[4];
    const int*   ps      = (const int*)d_in[5];
    const int*   pd      = (const int*)d_in[6];
    const int*   ns      = (const int*)d_in[7];
    const int*   nd      = (const int*)d_in[8];
    const float* w_proj  = (const float*)d_in[9];
    const float* b_proj  = (const float*)d_in[10];
    const float* w_self1 = (const float*)d_in[11];
    const float* w_neigh1= (const float*)d_in[12];
    const float* b1      = (const float*)d_in[13];
    const float* w_self2 = (const float*)d_in[14];
    const float* w_neigh2= (const float*)d_in[15];
    const float* b2      = (const float*)d_in[16];

    const int E0 = in_sizes[1];
    const int E1 = in_sizes[3];
    const int P  = in_sizes[5];
    const int Q  = in_sizes[7];
    float* out = (float*)d_out;

    ensure_host_resources();

    float *h0, *h1;
    __nv_bfloat16 *Xhi, *Xlo, *Yhi, *Ylo, *Zhi, *Zlo, *w;
    int *hist, *rowptr, *cursor, *csr, *blocksums;
    cudaGetSymbolAddress((void**)&h0,  g_h0);
    cudaGetSymbolAddress((void**)&h1,  g_h1);
    cudaGetSymbolAddress((void**)&Xhi, g_pXhi);
    cudaGetSymbolAddress((void**)&Xlo, g_pXlo);
    cudaGetSymbolAddress((void**)&Yhi, g_pYhi);
    cudaGetSymbolAddress((void**)&Ylo, g_pYlo);
    cudaGetSymbolAddress((void**)&Zhi, g_pZhi);
    cudaGetSymbolAddress((void**)&Zlo, g_pZlo);
    cudaGetSymbolAddress((void**)&hist, g_hist);
    cudaGetSymbolAddress((void**)&rowptr, g_rowptr);
    cudaGetSymbolAddress((void**)&cursor, g_cursor);
    cudaGetSymbolAddress((void**)&csr, g_csr);
    cudaGetSymbolAddress((void**)&blocksums, g_blocksums);
    cudaGetSymbolAddress((void**)&w, g_w);
    auto W = [&](int m, int part) { return w + ((size_t)m * 2 + part) * 128 * 128; };
    int* hist0 = hist;              int* hist1 = hist + N_NODES;
    int* rp0 = rowptr;              int* rp1 = rowptr + (N_NODES + 1);
    int* cur0 = cursor;             int* cur1 = cursor + N_NODES;
    int* csr0 = csr;                int* csr1 = csr + E_MAX;
    int* bs0 = blocksums;           int* bs1 = blocksums + SCAN_NB;

    cudaFuncSetAttribute(gemm_mma_kernel<0, 1, 1>, cudaFuncAttributeMaxDynamicSharedMemorySize, SMEM_MMA);
    cudaFuncSetAttribute(gemm_mma_kernel<1, 1, 1>, cudaFuncAttributeMaxDynamicSharedMemorySize, SMEM_MMA);
    cudaFuncSetAttribute(gemm_mma_kernel<1, 0, 0>, cudaFuncAttributeMaxDynamicSharedMemorySize, SMEM_MMA);

    const int gemm_grid = N_TILES256;
    const int gather_grid = (N_NODES * 32 + 255) / 256;

    // ---- fork: CSR builds for BOTH layers on side stream (depend only on edges) ----
    cudaEventRecord(g_evFork, 0);
    cudaStreamWaitEvent(g_s2, g_evFork, 0);
    zero_int_kernel<<<256, 256, 0, g_s2>>>(hist0, 2 * N_NODES);
    build_csr(g_s2, e0s, e0d, E0, hist0, rp0, cur0, csr0, bs0);
    cudaEventRecord(g_evCsr0, g_s2);
    build_csr(g_s2, e1s, e1d, E1, hist1, rp1, cur1, csr1, bs1);
    cudaEventRecord(g_evCsr1, g_s2);

    // ---- main stream: weight + feat prep (overlaps CSR builds) ----
    prep_w_all_kernel<<<320, 256>>>(w_proj, w_self1, w_neigh1, w_self2, w_neigh2, w);
    prep_feat_kernel<<<(int)((PLANE_ROWS * 16 + 255) / 256), 256>>>(feat, Xhi, Xlo, N_NODES);

    // proj: h0 = relu(feat @ w_proj + b_proj); emit Y = planes(h0)
    gemm_mma_kernel<0, 1, 1><<<gemm_grid, GTHREADS, SMEM_MMA>>>(
        Xhi, Xlo, W(0, 0), W(0, 1), nullptr, nullptr, nullptr, nullptr,
        b_proj, h0, Yhi, Ylo, N_NODES);

    // ---- layer 1 ----
    cudaStreamWaitEvent((cudaStream_t)0, g_evCsr0, 0);
    gather_mean_kernel<<<gather_grid, 256>>>(h0, csr0, rp0, Zhi, Zlo);
    // h1 = relu(h0 @ Wself1 + agg @ Wneigh1 + b1); emit X = planes(h1)
    gemm_mma_kernel<1, 1, 1><<<gemm_grid, GTHREADS, SMEM_MMA>>>(
        Yhi, Ylo, W(1, 0), W(1, 1), Zhi, Zlo, W(2, 0), W(2, 1),
        b1, h1, Xhi, Xlo, N_NODES);

    // ---- layer 2 ----
    cudaStreamWaitEvent((cudaStream_t)0, g_evCsr1, 0);
    gather_mean_kernel<<<gather_grid, 256>>>(h1, csr1, rp1, Zhi, Zlo);
    // h2 (into h0 buffer) = h1 @ Wself2 + agg @ Wneigh2 + b2
    gemm_mma_kernel<1, 0, 0><<<gemm_grid, GTHREADS, SMEM_MMA>>>(
        Xhi, Xlo, W(3, 0), W(3, 1), Zhi, Zlo, W(4, 0), W(4, 1),
        b2, h0, nullptr, nullptr, N_NODES);

    // ---- scores ----
    score_kernel<<<(P + Q + 7) / 8, 256>>>(h0, ps, pd, P, ns, nd, Q, out);
}

// round 14
// speedup vs baseline: 1.0737x; 1.0737x over previous
#include <cuda_runtime.h>
#include <cuda_bf16.h>
#include <cstdint>

#define N_NODES 100000
#define D 128
#define E_MAX 1600000
#define SCAN_CHUNK 1024
#define SCAN_NB ((N_NODES + SCAN_CHUNK - 1) / SCAN_CHUNK)   // 98
#define N_TILES ((N_NODES + 127) / 128)                      // 782
#define PLANE_ELEMS ((size_t)N_TILES * 128 * 128)            // padded to tile multiple

// ---------------- scratch (static device globals; no allocation) ----------------
__device__ float g_h0[(size_t)N_NODES * D];
__device__ float g_h1[(size_t)N_NODES * D];
// agg stored ONLY as split-bf16 planes (padded rows never written; outputs masked)
__device__ __nv_bfloat16 g_aggHi[PLANE_ELEMS];
__device__ __nv_bfloat16 g_aggLo[PLANE_ELEMS];
__device__ int   g_hist[2][N_NODES];
__device__ int   g_rowptr[2][N_NODES + 1];
__device__ int   g_cursor[2][N_NODES];
__device__ int   g_csr[2][E_MAX];
__device__ int   g_blocksums[2][SCAN_NB];
// pre-split weights, transposed (B[n][k] = W[k][n]), plain row-major [n][128] bf16
__device__ __nv_bfloat16 g_w[5][2][128 * 128];

// ---------------- host-side streams/events (host resources only; created once) ------
static cudaStream_t g_s2 = nullptr;
static cudaEvent_t  g_evFork = nullptr, g_evCsr0 = nullptr, g_evCsr1 = nullptr;
static void ensure_host_resources() {
    if (g_s2) return;
    cudaStreamCreateWithFlags(&g_s2, cudaStreamNonBlocking);
    cudaEventCreateWithFlags(&g_evFork, cudaEventDisableTiming);
    cudaEventCreateWithFlags(&g_evCsr0, cudaEventDisableTiming);
    cudaEventCreateWithFlags(&g_evCsr1, cudaEventDisableTiming);
}
static struct _InitOnce { _InitOnce() { ensure_host_resources(); } } g_initOnce;

// ================= helpers =================
__device__ __forceinline__ uint32_t smem_u32(const void* p) {
    uint32_t a;
    asm("{ .reg .u64 t; cvta.to.shared.u64 t, %1; cvt.u32.u64 %0, t; }" : "=r"(a) : "l"(p));
    return a;
}
__device__ __forceinline__ uint32_t pack_bf16x2(float x, float y) {
    uint32_t r;
    asm("cvt.rn.bf16x2.f32 %0, %1, %2;" : "=r"(r) : "f"(y), "f"(x));
    return r;
}
__device__ __forceinline__ void cp_async16(uint32_t dst, const void* src) {
    asm volatile("cp.async.cg.shared.global [%0], [%1], 16;" :: "r"(dst), "l"(src));
}
__device__ __forceinline__ void cp_async_wait_all() {
    asm volatile("cp.async.commit_group;");
    asm volatile("cp.async.wait_group 0;" ::: "memory");
}
// smem layout for a [128 rows x 64 cols] bf16 half-tile: 128B rows, 16B chunks
// XOR-swizzled by (r & 7) -> conflict-free ldmatrix (verified since R6)
__device__ __forceinline__ uint32_t chunk_off64(int r, int c) {
    return (uint32_t)r * 128u + (uint32_t)((c ^ (r & 7)) << 4);
}
__device__ __forceinline__ void ldsm_x4(uint32_t* f, uint32_t addr) {
    asm volatile("ldmatrix.sync.aligned.m8n8.x4.shared.b16 {%0,%1,%2,%3}, [%4];"
                 : "=r"(f[0]), "=r"(f[1]), "=r"(f[2]), "=r"(f[3]) : "r"(addr));
}
__device__ __forceinline__ void ldsm_x2(uint32_t* f, uint32_t addr) {
    asm volatile("ldmatrix.sync.aligned.m8n8.x2.shared.b16 {%0,%1}, [%2];"
                 : "=r"(f[0]), "=r"(f[1]) : "r"(addr));
}
__device__ __forceinline__ void mma_bf16(float* c, const uint32_t* a, const uint32_t* b) {
    asm volatile("mma.sync.aligned.m16n8k16.row.col.f32.bf16.bf16.f32 "
                 "{%0,%1,%2,%3}, {%4,%5,%6,%7}, {%8,%9}, {%0,%1,%2,%3};"
                 : "+f"(c[0]), "+f"(c[1]), "+f"(c[2]), "+f"(c[3])
                 : "r"(a[0]), "r"(a[1]), "r"(a[2]), "r"(a[3]), "r"(b[0]), "r"(b[1]));
}

// ================= weight prep (all 5 matrices in one launch) =================
__global__ void prep_w_all_kernel(const float* __restrict__ w0, const float* __restrict__ w1,
                                  const float* __restrict__ w2, const float* __restrict__ w3,
                                  const float* __restrict__ w4, __nv_bfloat16* __restrict__ out) {
    int g = blockIdx.x >> 6;                      // 64 blocks per matrix
    const float* W = (g == 0) ? w0 : (g == 1) ? w1 : (g == 2) ? w2 : (g == 3) ? w3 : w4;
    __nv_bfloat16* hi = out + (size_t)g * 2 * 16384;
    __nv_bfloat16* lo = hi + 16384;
    int e = (blockIdx.x & 63) * 256 + threadIdx.x;   // 0..16383
    int n = e >> 7, k = e & 127;
    float v = W[k * 128 + n];
    float h = __bfloat162float(__float2bfloat16_rn(v));
    hi[n * 128 + k] = __float2bfloat16_rn(h);
    lo[n * 128 + k] = __float2bfloat16_rn(v - h);
}

// ================= split-bf16 GEMM via mma.sync (R8/R12 internals, M=128, 2 CTA/SM) ===
#define SA_HI 0
#define SA_LO 16384
#define SB_HI 32768
#define SB_LO 49152
#define SMEM_MMA 65536

// stage one K=64 half: B planes via cp.async, A fp32 via load+split+STS
__device__ __forceinline__ void stage_half(
    const float* __restrict__ A,
    const __nv_bfloat16* __restrict__ Bhi, const __nv_bfloat16* __restrict__ Blo,
    uint32_t sb, int block_m, int khalf, int M, int tid)
{
#pragma unroll
    for (int j = 0; j < 8; j++) {
        int id = tid + j * 256;
        const char* plane = (const char*)((id & 1024) ? Blo : Bhi);
        int cid = id & 1023;
        int n = cid >> 3, c = cid & 7;
        const char* src = plane + (size_t)n * 256 + khalf * 128 + c * 16;
        uint32_t dst = sb + ((id & 1024) ? SB_LO : SB_HI) + chunk_off64(n, c);
        cp_async16(dst, src);
    }
#pragma unroll
    for (int j = 0; j < 4; j++) {
        int cid = tid + j * 256;           // 0..1023
        int r = cid >> 3, c = cid & 7;
        int gm = block_m + r;
        float4 v0 = make_float4(0.f, 0.f, 0.f, 0.f), v1 = v0;
        if (gm < M) {
            const float4* gp = (const float4*)(A + (size_t)gm * 128 + khalf * 64 + c * 8);
            v0 = gp[0]; v1 = gp[1];
        }
        float h0 = __bfloat162float(__float2bfloat16_rn(v0.x));
        float h1 = __bfloat162float(__float2bfloat16_rn(v0.y));
        float h2 = __bfloat162float(__float2bfloat16_rn(v0.z));
        float h3 = __bfloat162float(__float2bfloat16_rn(v0.w));
        float h4 = __bfloat162float(__float2bfloat16_rn(v1.x));
        float h5 = __bfloat162float(__float2bfloat16_rn(v1.y));
        float h6 = __bfloat162float(__float2bfloat16_rn(v1.z));
        float h7 = __bfloat162float(__float2bfloat16_rn(v1.w));
        uint4 hp, lp;
        hp.x = pack_bf16x2(h0, h1); hp.y = pack_bf16x2(h2, h3);
        hp.z = pack_bf16x2(h4, h5); hp.w = pack_bf16x2(h6, h7);
        lp.x = pack_bf16x2(v0.x - h0, v0.y - h1);
        lp.y = pack_bf16x2(v0.z - h2, v0.w - h3);
        lp.z = pack_bf16x2(v1.x - h4, v1.y - h5);
        lp.w = pack_bf16x2(v1.z - h6, v1.w - h7);
        uint32_t sw = chunk_off64(r, c);
        asm volatile("st.shared.v4.b32 [%0], {%1,%2,%3,%4};"
                     :: "r"(sb + SA_HI + sw), "r"(hp.x), "r"(hp.y), "r"(hp.z), "r"(hp.w));
        asm volatile("st.shared.v4.b32 [%0], {%1,%2,%3,%4};"
                     :: "r"(sb + SA_LO + sw), "r"(lp.x), "r"(lp.y), "r"(lp.z), "r"(lp.w));
    }
}

// stage one K=64 half where BOTH A and B are pre-split planes: pure cp.async
__device__ __forceinline__ void stage_half_planes(
    const __nv_bfloat16* __restrict__ Ahi, const __nv_bfloat16* __restrict__ Alo,
    const __nv_bfloat16* __restrict__ Bhi, const __nv_bfloat16* __restrict__ Blo,
    uint32_t sb, int block_m, int khalf, int tid)
{
#pragma unroll
    for (int j = 0; j < 8; j++) {                // B: 2048 chunks
        int id = tid + j * 256;
        const char* plane = (const char*)((id & 1024) ? Blo : Bhi);
        int cid = id & 1023;
        int n = cid >> 3, c = cid & 7;
        const char* src = plane + (size_t)n * 256 + khalf * 128 + c * 16;
        uint32_t dst = sb + ((id & 1024) ? SB_LO : SB_HI) + chunk_off64(n, c);
        cp_async16(dst, src);
    }
#pragma unroll
    for (int j = 0; j < 8; j++) {                // A: 2048 chunks (hi 1024 + lo 1024)
        int id = tid + j * 256;
        const char* plane = (const char*)((id & 1024) ? Alo : Ahi);
        int cid = id & 1023;
        int r = cid >> 3, c = cid & 7;
        const char* src = plane + (size_t)(block_m + r) * 256 + khalf * 128 + c * 16;
        uint32_t dst = sb + ((id & 1024) ? SA_LO : SA_HI) + chunk_off64(r, c);
        cp_async16(dst, src);
    }
}

__device__ __forceinline__ void mma_half(uint32_t sb, int wid, int lane, float acc[4][4][4]) {
    const int m_base = (wid & 1) * 64;
    const int n_base = (wid >> 1) * 32;
    const int ra = lane & 15;
    const int kca = lane >> 4;
    const int nb = lane & 7;
    const int kcb = (lane >> 3) & 1;
#pragma unroll
    for (int kk = 0; kk < 4; kk++) {
        uint32_t bh[4][2], bl[4][2];
#pragma unroll
        for (int in = 0; in < 4; in++) {
            int n = n_base + in * 8 + nb;
            uint32_t a = sb + chunk_off64(n, 2 * kk + kcb);
            ldsm_x2(bh[in], a + SB_HI);
            ldsm_x2(bl[in], a + SB_LO);
        }
#pragma unroll
        for (int im = 0; im < 4; im++) {
            uint32_t ah[4], al[4];
            int r = m_base + im * 16 + ra;
            uint32_t a = sb + chunk_off64(r, 2 * kk + kca);
            ldsm_x4(ah, a + SA_HI);
            ldsm_x4(al, a + SA_LO);
#pragma unroll
            for (int in = 0; in < 4; in++) {
                mma_bf16(acc[im][in], ah, bh[in]);
                mma_bf16(acc[im][in], ah, bl[in]);
                mma_bf16(acc[im][in], al, bh[in]);
            }
        }
    }
}

// DUAL=0: C = act(A1@W1 + bias); DUAL=1: C = act(A1@W1 + Aplanes@W2 + bias)
template<int DUAL, int RELU>
__global__ void __launch_bounds__(256, 2) gemm_mma_kernel(
    const float* __restrict__ A1,
    const __nv_bfloat16* __restrict__ B1hi, const __nv_bfloat16* __restrict__ B1lo,
    const __nv_bfloat16* __restrict__ A2hi, const __nv_bfloat16* __restrict__ A2lo,
    const __nv_bfloat16* __restrict__ B2hi, const __nv_bfloat16* __restrict__ B2lo,
    const float* __restrict__ bias, float* __restrict__ C, int M)
{
    extern __shared__ __align__(128) char smem[];
    const uint32_t sb = smem_u32(smem);
    const int tid = threadIdx.x;
    const int wid = tid >> 5;
    const int lane = tid & 31;
    const int block_m = blockIdx.x * 128;

    float acc[4][4][4];
#pragma unroll
    for (int im = 0; im < 4; im++)
#pragma unroll
        for (int in = 0; in < 4; in++)
#pragma unroll
            for (int q = 0; q < 4; q++) acc[im][in][q] = 0.0f;

#pragma unroll
    for (int kh = 0; kh < 2; kh++) {
        stage_half(A1, B1hi, B1lo, sb, block_m, kh, M, tid);
        cp_async_wait_all();
        __syncthreads();
        mma_half(sb, wid, lane, acc);
        __syncthreads();
    }
    if (DUAL) {
#pragma unroll
        for (int kh = 0; kh < 2; kh++) {
            stage_half_planes(A2hi, A2lo, B2hi, B2lo, sb, block_m, kh, tid);
            cp_async_wait_all();
            __syncthreads();
            mma_half(sb, wid, lane, acc);
            __syncthreads();
        }
    }

    const int m_base = block_m + (wid & 1) * 64;
    const int n_base = (wid >> 1) * 32;
    const int rq = lane >> 2;
    const int cq = (lane & 3) * 2;
#pragma unroll
    for (int im = 0; im < 4; im++) {
#pragma unroll
        for (int in = 0; in < 4; in++) {
            int gn = n_base + in * 8 + cq;
            float bx = bias[gn], by = bias[gn + 1];
#pragma unroll
            for (int half = 0; half < 2; half++) {
                int gm = m_base + im * 16 + rq + half * 8;
                if (gm >= M) continue;
                float x = acc[im][in][half * 2 + 0] + bx;
                float y = acc[im][in][half * 2 + 1] + by;
                if (RELU) { x = fmaxf(x, 0.f); y = fmaxf(y, 0.f); }
                *(float2*)(C + (size_t)gm * 128 + gn) = make_float2(x, y);
            }
        }
    }
}

// ================= graph aggregation =================
__global__ void zero_int_kernel(int* __restrict__ p, int n) {
    int i = blockIdx.x * blockDim.x + threadIdx.x;
    int stride = gridDim.x * blockDim.x;
    for (; i < n; i += stride) p[i] = 0;
}

__global__ void hist_kernel(const int* __restrict__ dst, int* __restrict__ hist, int E) {
    int i = blockIdx.x * blockDim.x + threadIdx.x;
    if (i >= E) return;
    atomicAdd(&hist[dst[i]], 1);
}

__global__ void scan1_kernel(const int* __restrict__ hist, int* __restrict__ blocksums) {
    __shared__ int sh[256];
    int t = threadIdx.x;
    int base = blockIdx.x * SCAN_CHUNK + t * 4;
    int s = 0;
#pragma unroll
    for (int j = 0; j < 4; j++) {
        int idx = base + j;
        if (idx < N_NODES) s += hist[idx];
    }
    sh[t] = s;
    __syncthreads();
    for (int o = 128; o > 0; o >>= 1) {
        if (t < o) sh[t] += sh[t + o];
        __syncthreads();
    }
    if (t == 0) blocksums[blockIdx.x] = sh[0];
}

__global__ void scan2_kernel(int* __restrict__ blocksums, int nb, int* __restrict__ rowptr) {
    if (threadIdx.x == 0 && blockIdx.x == 0) {
        int run = 0;
        for (int i = 0; i < nb; i++) {
            int v = blocksums[i];
            blocksums[i] = run;
            run += v;
        }
        rowptr[N_NODES] = run;
    }
}

__global__ void scan3_kernel(const int* __restrict__ hist, const int* __restrict__ blocksums,
                             int* __restrict__ rowptr, int* __restrict__ cursor) {
    __shared__ int sh[256];
    int t = threadIdx.x;
    int base = blockIdx.x * SCAN_CHUNK + t * 4;
    int v[4];
    int s = 0;
#pragma unroll
    for (int j = 0; j < 4; j++) {
        int idx = base + j;
        v[j] = (idx < N_NODES) ? hist[idx] : 0;
        s += v[j];
    }
    sh[t] = s;
    __syncthreads();
    int val = s;
    for (int o = 1; o < 256; o <<= 1) {
        int other = (t >= o) ? sh[t - o] : 0;
        __syncthreads();
        val += other;
        sh[t] = val;
        __syncthreads();
    }
    int texcl = val - s;
    int off = blocksums[blockIdx.x] + texcl;
#pragma unroll
    for (int j = 0; j < 4; j++) {
        int idx = base + j;
        if (idx < N_NODES) {
            rowptr[idx] = off;
            cursor[idx] = off;
        }
        off += v[j];
    }
}

__global__ void fill_kernel(const int* __restrict__ src, const int* __restrict__ dst,
                            int* __restrict__ cursor, int* __restrict__ csr, int E) {
    int i = blockIdx.x * blockDim.x + threadIdx.x;
    if (i >= E) return;
    int p = atomicAdd(&cursor[dst[i]], 1);
    csr[p] = src[i];
}

// gather + mean; x4-unrolled neighbor loop for MLP; writes split-bf16 planes.
// Accumulation order identical to the R12 version (bitwise-same result).
__global__ void __launch_bounds__(256) gather_mean_kernel(
    const float* __restrict__ h, const int* __restrict__ csr,
    const int* __restrict__ rowptr,
    __nv_bfloat16* __restrict__ Ahi, __nv_bfloat16* __restrict__ Alo)
{
    int gw = (blockIdx.x * blockDim.x + threadIdx.x) >> 5;
    int lane = threadIdx.x & 31;
    if (gw >= N_NODES) return;
    int n0 = rowptr[gw];
    int n1 = rowptr[gw + 1];
    float4 acc = make_float4(0.f, 0.f, 0.f, 0.f);
    for (int base = n0; base < n1; base += 32) {
        int idx = base + lane;
        int sj = (idx < n1) ? csr[idx] : 0;
        int cnt = min(32, n1 - base);
        int t = 0;
        for (; t + 4 <= cnt; t += 4) {
            int s0 = __shfl_sync(0xFFFFFFFFu, sj, t + 0);
            int s1 = __shfl_sync(0xFFFFFFFFu, sj, t + 1);
            int s2 = __shfl_sync(0xFFFFFFFFu, sj, t + 2);
            int s3 = __shfl_sync(0xFFFFFFFFu, sj, t + 3);
            float4 v0 = ((const float4*)(h + (size_t)s0 * 128))[lane];
            float4 v1 = ((const float4*)(h + (size_t)s1 * 128))[lane];
            float4 v2 = ((const float4*)(h + (size_t)s2 * 128))[lane];
            float4 v3 = ((const float4*)(h + (size_t)s3 * 128))[lane];
            acc.x += v0.x; acc.y += v0.y; acc.z += v0.z; acc.w += v0.w;
            acc.x += v1.x; acc.y += v1.y; acc.z += v1.z; acc.w += v1.w;
            acc.x += v2.x; acc.y += v2.y; acc.z += v2.z; acc.w += v2.w;
            acc.x += v3.x; acc.y += v3.y; acc.z += v3.z; acc.w += v3.w;
        }
        for (; t < cnt; t++) {
            int s = __shfl_sync(0xFFFFFFFFu, sj, t);
            float4 v = ((const float4*)(h + (size_t)s * 128))[lane];
            acc.x += v.x; acc.y += v.y; acc.z += v.z; acc.w += v.w;
        }
    }
    float inv = (n1 > n0) ? 1.0f / (float)(n1 - n0) : 0.0f;
    acc.x *= inv; acc.y *= inv; acc.z *= inv; acc.w *= inv;
    float hx = __bfloat162float(__float2bfloat16_rn(acc.x));
    float hy = __bfloat162float(__float2bfloat16_rn(acc.y));
    float hz = __bfloat162float(__float2bfloat16_rn(acc.z));
    float hw = __bfloat162float(__float2bfloat16_rn(acc.w));
    size_t idx = (size_t)gw * 128 + lane * 4;
    uint2 hp, lp;
    hp.x = pack_bf16x2(hx, hy);            hp.y = pack_bf16x2(hz, hw);
    lp.x = pack_bf16x2(acc.x - hx, acc.y - hy);
    lp.y = pack_bf16x2(acc.z - hz, acc.w - hw);
    *(uint2*)(Ahi + idx) = hp;
    *(uint2*)(Alo + idx) = lp;
}

__global__ void score_kernel(const float* __restrict__ h,
                             const int* __restrict__ pa, const int* __restrict__ pb, int P,
                             const int* __restrict__ na, const int* __restrict__ nb, int Q,
                             float* __restrict__ out)
{
    int gw = (blockIdx.x * blockDim.x + threadIdx.x) >> 5;
    int lane = threadIdx.x & 31;
    if (gw >= P + Q) return;
    int ia, ib;
    if (gw < P) { ia = pa[gw]; ib = pb[gw]; }
    else        { ia = na[gw - P]; ib = nb[gw - P]; }
    float4 va = ((const float4*)(h + (size_t)ia * 128))[lane];
    float4 vb = ((const float4*)(h + (size_t)ib * 128))[lane];
    float s = va.x * vb.x + va.y * vb.y + va.z * vb.z + va.w * vb.w;
#pragma unroll
    for (int o = 16; o > 0; o >>= 1) s += __shfl_xor_sync(0xFFFFFFFFu, s, o);
    if (lane == 0) out[gw] = s;
}

// ---------------- CSR build (all launches on stream s) ----------------
static void build_csr(cudaStream_t s, const int* src, const int* dst, int E,
                      int* hist, int* rowptr, int* cursor, int* csr, int* blocksums)
{
    hist_kernel<<<(E + 255) / 256, 256, 0, s>>>(dst, hist, E);
    scan1_kernel<<<SCAN_NB, 256, 0, s>>>(hist, blocksums);
    scan2_kernel<<<1, 32, 0, s>>>(blocksums, SCAN_NB, rowptr);
    scan3_kernel<<<SCAN_NB, 256, 0, s>>>(hist, blocksums, rowptr, cursor);
    fill_kernel<<<(E + 255) / 256, 256, 0, s>>>(src, dst, cursor, csr, E);
}

extern "C" void kernel_launch(void* const* d_in, const int* in_sizes, int n_in,
                              void* d_out, int out_size)
{
    const float* feat    = (const float*)d_in[0];
    const int*   e0s     = (const int*)d_in[1];
    const int*   e0d     = (const int*)d_in[2];
    const int*   e1s     = (const int*)d_in[3];
    const int*   e1d     = (const int*)d_in[4];
    const int*   ps      = (const int*)d_in[5];
    const int*   pd      = (const int*)d_in[6];
    const int*   ns      = (const int*)d_in[7];
    const int*   nd      = (const int*)d_in[8];
    const float* w_proj  = (const float*)d_in[9];
    const float* b_proj  = (const float*)d_in[10];
    const float* w_self1 = (const float*)d_in[11];
    const float* w_neigh1= (const float*)d_in[12];
    const float* b1      = (const float*)d_in[13];
    const float* w_self2 = (const float*)d_in[14];
    const float* w_neigh2= (const float*)d_in[15];
    const float* b2      = (const float*)d_in[16];

    const int E0 = in_sizes[1];
    const int E1 = in_sizes[3];
    const int P  = in_sizes[5];
    const int Q  = in_sizes[7];
    float* out = (float*)d_out;

    ensure_host_resources();

    float *h0, *h1;
    __nv_bfloat16 *aggHi, *aggLo;
    int *hist, *rowptr, *cursor, *csr, *blocksums;
    __nv_bfloat16* w;
    cudaGetSymbolAddress((void**)&h0,  g_h0);
    cudaGetSymbolAddress((void**)&h1,  g_h1);
    cudaGetSymbolAddress((void**)&aggHi, g_aggHi);
    cudaGetSymbolAddress((void**)&aggLo, g_aggLo);
    cudaGetSymbolAddress((void**)&hist, g_hist);
    cudaGetSymbolAddress((void**)&rowptr, g_rowptr);
    cudaGetSymbolAddress((void**)&cursor, g_cursor);
    cudaGetSymbolAddress((void**)&csr, g_csr);
    cudaGetSymbolAddress((void**)&blocksums, g_blocksums);
    cudaGetSymbolAddress((void**)&w, g_w);
    auto W = [&](int m, int part) { return w + ((size_t)m * 2 + part) * 128 * 128; };
    int* hist0 = hist;              int* hist1 = hist + N_NODES;
    int* rp0 = rowptr;              int* rp1 = rowptr + (N_NODES + 1);
    int* cur0 = cursor;             int* cur1 = cursor + N_NODES;
    int* csr0 = csr;                int* csr1 = csr + E_MAX;
    int* bs0 = blocksums;           int* bs1 = blocksums + SCAN_NB;

    cudaFuncSetAttribute(gemm_mma_kernel<0, 1>, cudaFuncAttributeMaxDynamicSharedMemorySize, SMEM_MMA);
    cudaFuncSetAttribute(gemm_mma_kernel<1, 1>, cudaFuncAttributeMaxDynamicSharedMemorySize, SMEM_MMA);
    cudaFuncSetAttribute(gemm_mma_kernel<1, 0>, cudaFuncAttributeMaxDynamicSharedMemorySize, SMEM_MMA);

    const int gemm_grid = N_TILES;
    const int gather_grid = (N_NODES * 32 + 255) / 256;

    // ---- fork: CSR builds for BOTH layers on side stream (depend only on edges) ----
    cudaEventRecord(g_evFork, 0);
    cudaStreamWaitEvent(g_s2, g_evFork, 0);

    zero_int_kernel<<<256, 256, 0, g_s2>>>(hist0, 2 * N_NODES);   // both hists contiguous
    build_csr(g_s2, e0s, e0d, E0, hist0, rp0, cur0, csr0, bs0);
    cudaEventRecord(g_evCsr0, g_s2);
    build_csr(g_s2, e1s, e1d, E1, hist1, rp1, cur1, csr1, bs1);
    cudaEventRecord(g_evCsr1, g_s2);

    // ---- main stream: weights + proj GEMM (overlaps CSR builds) ----
    prep_w_all_kernel<<<320, 256>>>(w_proj, w_self1, w_neigh1, w_self2, w_neigh2, w);

    gemm_mma_kernel<0, 1><<<gemm_grid, 256, SMEM_MMA>>>(
        feat, W(0, 0), W(0, 1), nullptr, nullptr, nullptr, nullptr, b_proj, h0, N_NODES);

    // ---- layer 1 ----
    cudaStreamWaitEvent((cudaStream_t)0, g_evCsr0, 0);
    gather_mean_kernel<<<gather_grid, 256>>>(h0, csr0, rp0, aggHi, aggLo);
    gemm_mma_kernel<1, 1><<<gemm_grid, 256, SMEM_MMA>>>(
        h0, W(1, 0), W(1, 1), aggHi, aggLo, W(2, 0), W(2, 1), b1, h1, N_NODES);

    // ---- layer 2 ----
    cudaStreamWaitEvent((cudaStream_t)0, g_evCsr1, 0);
    gather_mean_kernel<<<gather_grid, 256>>>(h1, csr1, rp1, aggHi, aggLo);
    gemm_mma_kernel<1, 0><<<gemm_grid, 256, SMEM_MMA>>>(
        h1, W(3, 0), W(3, 1), aggHi, aggLo, W(4, 0), W(4, 1), b2, h0, N_NODES);

    // ---- scores ----
    score_kernel<<<(P + Q + 7) / 8, 256>>>(h0, ps, pd, P, ns, nd, Q, out);
}